// round 3
// baseline (speedup 1.0000x reference)
#include <cuda_runtime.h>

// Shapes: probs (2,2,32,512,512) fp32, gt_mask (2,32,512,512) int32.
// Output: scalar fp32 = mean over all of (probs - onehot(target))^2,
// target = (gt == 1) since ignore_index=2 -> 0 and clamp [0,1].
//
// Single-kernel threadfence reduction: each block writes a partial,
// the last block to finish reduces all partials and writes the scalar,
// then resets the arrival counter (graph-replay deterministic).

constexpr int DHW      = 32 * 512 * 512;   // 8388608 = 2^23
constexpr int NGT      = 2 * DHW;          // 16777216
constexpr int VEC      = NGT / 4;          // 4194304 int4/float4 groups
constexpr int DHW4     = DHW / 4;          // 2097152 = 2^21
constexpr int BLOCKS   = 1024;
constexpr int THREADS  = 256;

__device__ float g_partials[BLOCKS];
__device__ unsigned int g_count;   // zero-initialized at module load; reset by last block

__device__ __forceinline__ float warp_sum(float v) {
    #pragma unroll
    for (int o = 16; o > 0; o >>= 1)
        v += __shfl_xor_sync(0xFFFFFFFFu, v, o);
    return v;
}

__global__ __launch_bounds__(THREADS) void mse_fused_kernel(
    const float* __restrict__ probs, const int* __restrict__ gt,
    float* __restrict__ out)
{
    const float4* __restrict__ p4 = reinterpret_cast<const float4*>(probs);
    const int4*   __restrict__ g4 = reinterpret_cast<const int4*>(gt);

    float acc = 0.0f;
    const int stride = gridDim.x * blockDim.x;
    for (int idx = blockIdx.x * blockDim.x + threadIdx.x; idx < VEC; idx += stride) {
        int4 g = g4[idx];
        int b = idx >> 21;            // DHW4 = 2^21
        int r = idx & (DHW4 - 1);
        // probs layout (B, C, D, H, W): channel stride = DHW
        float4 p0 = p4[(size_t)(2 * b    ) * DHW4 + r];  // c = 0
        float4 p1 = p4[(size_t)(2 * b + 1) * DHW4 + r];  // c = 1

        // onehot: oh0 = (gt != 1), oh1 = (gt == 1)
        float d;
        d = p0.x - (float)(g.x != 1); acc = fmaf(d, d, acc);
        d = p1.x - (float)(g.x == 1); acc = fmaf(d, d, acc);
        d = p0.y - (float)(g.y != 1); acc = fmaf(d, d, acc);
        d = p1.y - (float)(g.y == 1); acc = fmaf(d, d, acc);
        d = p0.z - (float)(g.z != 1); acc = fmaf(d, d, acc);
        d = p1.z - (float)(g.z == 1); acc = fmaf(d, d, acc);
        d = p0.w - (float)(g.w != 1); acc = fmaf(d, d, acc);
        d = p1.w - (float)(g.w == 1); acc = fmaf(d, d, acc);
    }

    // Block reduction: warp shuffles -> smem -> warp 0
    __shared__ float smem[THREADS / 32];
    __shared__ bool s_last;
    acc = warp_sum(acc);
    int lane = threadIdx.x & 31;
    int wid  = threadIdx.x >> 5;
    if (lane == 0) smem[wid] = acc;
    __syncthreads();
    if (threadIdx.x == 0) {
        float v = 0.0f;
        #pragma unroll
        for (int i = 0; i < THREADS / 32; i++) v += smem[i];
        g_partials[blockIdx.x] = v;
        // Make the partial visible before announcing arrival.
        __threadfence();
        unsigned int prev = atomicAdd(&g_count, 1u);
        s_last = (prev == (unsigned int)(gridDim.x - 1));
    }
    __syncthreads();

    if (s_last) {
        // Last block: reduce all 1024 partials. Each thread takes 4.
        __threadfence();  // acquire: ensure we see all partials
        float v = 0.0f;
        #pragma unroll
        for (int i = 0; i < BLOCKS / THREADS; i++)
            v += g_partials[threadIdx.x + i * THREADS];
        v = warp_sum(v);
        if (lane == 0) smem[wid] = v;
        __syncthreads();
        if (threadIdx.x == 0) {
            float t = 0.0f;
            #pragma unroll
            for (int i = 0; i < THREADS / 32; i++) t += smem[i];
            out[0] = t * (1.0f / 33554432.0f);  // 1 / (B*C*D*H*W)
            g_count = 0;  // restore invariant for next graph replay
        }
    }
}

extern "C" void kernel_launch(void* const* d_in, const int* in_sizes, int n_in,
                              void* d_out, int out_size)
{
    const float* probs = (const float*)d_in[0];
    const int*   gt    = (const int*)d_in[1];
    float*       out   = (float*)d_out;

    mse_fused_kernel<<<BLOCKS, THREADS>>>(probs, gt, out);
}